// round 8
// baseline (speedup 1.0000x reference)
#include <cuda_runtime.h>
#include <cstdint>

// Masked cumsum along dim 1: out[b,:] = cumsum(where(mask, x, 0))
// B=256 rows, N=131072 cols, fp32 x, int32 mask.
//
// R5 structure (best: 63.6us, DRAM 79.5%) with chunk doubled to 8192 elems
// (VPT 16, 16 iterations): halves per-byte barrier/scan/carry-chain overhead
// and doubles in-flight prefetch (64KB/CTA). Warp owns a contiguous 512-float
// segment per chunk: 4 rounds of lane-consecutive float4/int4, every
// LDG/STG.128 a perfect 4-line access. Scan: lane(4) -> 4 ILP warp scans ->
// round chain(4) -> redundant-per-warp CTA scan (shfl over 16 totals, ONE
// barrier) -> running carry. Streaming cache hints.

#define CS_THREADS 512
#define CS_NWARPS  16
#define CS_ROUNDS  4
#define CS_CHUNK   8192                   // 512 thr * 16 elems
#define CS_NCOLS   131072
#define CS_ITERS   (CS_NCOLS / CS_CHUNK)  // 16

__global__ __launch_bounds__(CS_THREADS, 2)
void masked_cumsum_kernel(const float* __restrict__ x,
                          const int* __restrict__ mask,
                          float* __restrict__ out) {
    __shared__ float shW[2][CS_NWARPS];   // [buf][w] = warp w chunk total

    const int row = blockIdx.x;
    const size_t roff4 = (size_t)row * (CS_NCOLS / 4);
    const float4* __restrict__ x4 = reinterpret_cast<const float4*>(x) + roff4;
    const int4*   __restrict__ m4 = reinterpret_cast<const int4*>(mask) + roff4;
    float4*       __restrict__ o4 = reinterpret_cast<float4*>(out) + roff4;

    const int tid  = threadIdx.x;
    const int lane = tid & 31;
    const int warp = tid >> 5;
    // Warp w owns floats [w*512, w*512+512) of each chunk:
    // round r (0..3), lane l -> float4 index w*128 + r*32 + l (coalesced)
    const int wbase = warp * 128 + lane;

    float carry = 0.0f;

    // Prefetch chunk 0 (4 x4 rounds + 4 mask rounds)
    float4 pa[CS_ROUNDS];
    int4   pm[CS_ROUNDS];
    #pragma unroll
    for (int b = 0; b < CS_ROUNDS; ++b) {
        pa[b] = __ldcs(&x4[wbase + b * 32]);
        pm[b] = __ldcs(&m4[wbase + b * 32]);
    }

    for (int it = 0; it < CS_ITERS; ++it) {
        float4 xa[CS_ROUNDS];
        int4   ma[CS_ROUNDS];
        #pragma unroll
        for (int b = 0; b < CS_ROUNDS; ++b) { xa[b] = pa[b]; ma[b] = pm[b]; }

        // Issue next chunk's loads immediately; consumed next iteration.
        if (it + 1 < CS_ITERS) {
            const int nb = (it + 1) * (CS_CHUNK / 4) + wbase;
            #pragma unroll
            for (int b = 0; b < CS_ROUNDS; ++b) {
                pa[b] = __ldcs(&x4[nb + b * 32]);
                pm[b] = __ldcs(&m4[nb + b * 32]);
            }
        }

        // Apply mask (each int32 is 0 or 1) + lane-local inclusive scans
        float v[CS_ROUNDS][4];
        #pragma unroll
        for (int b = 0; b < CS_ROUNDS; ++b) {
            v[b][0] = ma[b].x ? xa[b].x : 0.f;
            v[b][1] = ma[b].y ? xa[b].y : 0.f;
            v[b][2] = ma[b].z ? xa[b].z : 0.f;
            v[b][3] = ma[b].w ? xa[b].w : 0.f;
            v[b][1] += v[b][0];
            v[b][2] += v[b][1];
            v[b][3] += v[b][2];
        }

        // 4 independent warp scans (ILP), then chain round totals
        float lexcl[CS_ROUNDS], T[CS_ROUNDS];
        {
            float i0 = v[0][3], i1 = v[1][3], i2 = v[2][3], i3 = v[3][3];
            #pragma unroll
            for (int d = 1; d < 32; d <<= 1) {
                float n0 = __shfl_up_sync(0xffffffffu, i0, d);
                float n1 = __shfl_up_sync(0xffffffffu, i1, d);
                float n2 = __shfl_up_sync(0xffffffffu, i2, d);
                float n3 = __shfl_up_sync(0xffffffffu, i3, d);
                if (lane >= d) { i0 += n0; i1 += n1; i2 += n2; i3 += n3; }
            }
            lexcl[0] = i0 - v[0][3]; lexcl[1] = i1 - v[1][3];
            lexcl[2] = i2 - v[2][3]; lexcl[3] = i3 - v[3][3];
            T[0] = __shfl_sync(0xffffffffu, i0, 31);
            T[1] = __shfl_sync(0xffffffffu, i1, 31);
            T[2] = __shfl_sync(0xffffffffu, i2, 31);
            T[3] = __shfl_sync(0xffffffffu, i3, 31);
        }
        float rExcl[CS_ROUNDS];
        rExcl[0] = 0.f;
        rExcl[1] = T[0];
        rExcl[2] = T[0] + T[1];
        rExcl[3] = rExcl[2] + T[2];
        const float warpTotal = rExcl[3] + T[3];

        const int buf = it & 1;
        if (lane == 0) shW[buf][warp] = warpTotal;
        __syncthreads();

        // Redundant-per-warp CTA scan of the 16 warp totals (R5-proven)
        float w = (lane < CS_NWARPS) ? shW[buf][lane] : 0.f;
        float wincl = w;
        #pragma unroll
        for (int d = 1; d < CS_NWARPS; d <<= 1) {
            float n = __shfl_up_sync(0xffffffffu, wincl, d);
            if (lane >= d) wincl += n;
        }
        const float wexcl      = __shfl_sync(0xffffffffu, wincl, warp) -
                                 __shfl_sync(0xffffffffu, w,     warp);
        const float chunkTotal = __shfl_sync(0xffffffffu, wincl, CS_NWARPS - 1);

        const float base0 = carry + wexcl;
        carry += chunkTotal;

        const int ob = it * (CS_CHUNK / 4) + wbase;
        #pragma unroll
        for (int b = 0; b < CS_ROUNDS; ++b) {
            const float base = base0 + rExcl[b] + lexcl[b];
            float4 o;
            o.x = v[b][0] + base;
            o.y = v[b][1] + base;
            o.z = v[b][2] + base;
            o.w = v[b][3] + base;
            __stcs(&o4[ob + b * 32], o);
        }
        // No trailing barrier: iter i+2's STS to this buf is fenced by iter i+1's bar.
    }
}

extern "C" void kernel_launch(void* const* d_in, const int* in_sizes, int n_in,
                              void* d_out, int out_size) {
    const float* x    = (const float*)d_in[0];
    const int*   mask = (const int*)d_in[1];
    float*       out  = (float*)d_out;
    const int rows = out_size / CS_NCOLS;   // 256
    masked_cumsum_kernel<<<rows, CS_THREADS>>>(x, mask, out);
}